// round 3
// baseline (speedup 1.0000x reference)
#include <cuda_runtime.h>
#include <stdint.h>

#define B_    32
#define HW_   225
#define C_    128
#define OUTH  7
#define OUTW  7
#define ITERS 10

// Scratch for pooled [32, 8, 8, 128] (device global: no allocations allowed)
__device__ float g_pooled[B_ * 8 * 8 * C_];

__device__ __forceinline__ float4 fmax4(float4 a, float4 b) {
    return make_float4(fmaxf(a.x, b.x), fmaxf(a.y, b.y),
                       fmaxf(a.z, b.z), fmaxf(a.w, b.w));
}

__device__ __forceinline__ float neg_inf() { return __int_as_float(0xff800000); }

// -----------------------------------------------------------------------------
// Kernel 1: max pool [32,225,225,128] -> [32,8,8,128]
// window = stride = 32, SAME padding (pad_lo=15, pad_hi=16), windows disjoint.
// Block = one pooled cell (b, i, j). 256 threads:
//   lane (tid&31)  -> channel quad (float4)  => warp reads 512B contiguous/pixel
//   rg   (tid>>5)  -> strides window rows by 8
// -----------------------------------------------------------------------------
__global__ void __launch_bounds__(256) pool_kernel(const float* __restrict__ x) {
    const int cell = blockIdx.x;      // 0..63
    const int b    = blockIdx.y;      // 0..31
    const int i = cell >> 3, j = cell & 7;

    int h0 = i * 32 - 15; if (h0 < 0)   h0 = 0;
    int h1 = i * 32 + 17; if (h1 > HW_) h1 = HW_;
    int w0 = j * 32 - 15; if (w0 < 0)   w0 = 0;
    int w1 = j * 32 + 17; if (w1 > HW_) w1 = HW_;

    const int lane = threadIdx.x & 31;
    const int rg   = threadIdx.x >> 5;

    const float4* __restrict__ base4 = (const float4*)x;
    float4 acc = make_float4(neg_inf(), neg_inf(), neg_inf(), neg_inf());

    const int nw = w1 - w0;
    for (int h = h0 + rg; h < h1; h += 8) {
        const float4* p = base4 + ((size_t)((b * HW_ + h) * HW_ + w0)) * 32 + lane;
        #pragma unroll 4
        for (int w = 0; w < nw; ++w) {
            acc = fmax4(acc, p[0]);
            p += 32;   // next pixel: 128 floats = 32 float4
        }
    }

    __shared__ float4 part[8][32];
    part[rg][lane] = acc;
    __syncthreads();

    if (rg == 0) {
        float4 m = part[0][lane];
        #pragma unroll
        for (int k = 1; k < 8; ++k) m = fmax4(m, part[k][lane]);
        ((float4*)g_pooled)[((b * 8 + i) * 8 + j) * 32 + lane] = m;
    }
}

// -----------------------------------------------------------------------------
// Kernel 2: combine pooled [32,8,8,128] -> out [32,7,7,128]
// For each iteration it with merge indices (i, j):
//   out row r uses pooled row r if r<i, max(row i,row i+1) if r==i, row r+1 if r>i
//   => include row r  iff r<=i, include row r+1 iff r>=i  (cols symmetric)
// Sum over 10 iterations, divide by 10.
// -----------------------------------------------------------------------------
struct IdxPack { int ii[ITERS]; int jj[ITERS]; };

__global__ void __launch_bounds__(256) combine_kernel(float* __restrict__ out, IdxPack ip) {
    const int t = blockIdx.x * blockDim.x + threadIdx.x;   // [0, 32*7*7*32)
    if (t >= B_ * OUTH * OUTW * 32) return;

    const int q    = t & 31;          // channel quad
    const int cellc = t >> 5;
    const int c = cellc % OUTW;
    const int r = (cellc / OUTW) % OUTH;
    const int b = cellc / (OUTW * OUTH);

    const float4* P = ((const float4*)g_pooled) + ((b * 8 + r) * 8 + c) * 32 + q;
    const float4 p00 = P[0];          // (r,   c)
    const float4 p01 = P[32];         // (r,   c+1)
    const float4 p10 = P[8 * 32];     // (r+1, c)
    const float4 p11 = P[9 * 32];     // (r+1, c+1)

    float4 sum = make_float4(0.f, 0.f, 0.f, 0.f);
    #pragma unroll
    for (int it = 0; it < ITERS; ++it) {
        const int mi = ip.ii[it], mj = ip.jj[it];
        const bool r0 = (r <= mi), r1 = (r >= mi);
        const bool c0 = (c <= mj), c1 = (c >= mj);
        float4 v = make_float4(neg_inf(), neg_inf(), neg_inf(), neg_inf());
        if (r0 && c0) v = fmax4(v, p00);
        if (r0 && c1) v = fmax4(v, p01);
        if (r1 && c0) v = fmax4(v, p10);
        if (r1 && c1) v = fmax4(v, p11);
        sum.x += v.x; sum.y += v.y; sum.z += v.z; sum.w += v.w;
    }

    float4 o = make_float4(sum.x / (float)ITERS, sum.y / (float)ITERS,
                           sum.z / (float)ITERS, sum.w / (float)ITERS);
    ((float4*)out)[t] = o;
}

// -----------------------------------------------------------------------------
// Host: exact replication of np.random.RandomState(seed).randint(0, 7)
// Legacy path: init_genrand seeding (seed < 2^32); bounded draw uses the
// 32-bit generator with masked rejection (mask=7, reject value 7).
// -----------------------------------------------------------------------------
namespace {
struct MT19937 {
    uint32_t mt[624];
    int idx;
    explicit MT19937(uint32_t s) {
        mt[0] = s;
        for (uint32_t k = 1; k < 624; ++k)
            mt[k] = 1812433253u * (mt[k - 1] ^ (mt[k - 1] >> 30)) + k;
        idx = 624;
    }
    uint32_t next() {
        if (idx >= 624) {
            for (int k = 0; k < 624; ++k) {
                uint32_t y = (mt[k] & 0x80000000u) | (mt[(k + 1) % 624] & 0x7fffffffu);
                uint32_t v = mt[(k + 397) % 624] ^ (y >> 1);
                if (y & 1u) v ^= 0x9908b0dfu;
                mt[k] = v;
            }
            idx = 0;
        }
        uint32_t y = mt[idx++];
        y ^= y >> 11;
        y ^= (y << 7)  & 0x9d2c5680u;
        y ^= (y << 15) & 0xefc60000u;
        y ^= y >> 18;
        return y;
    }
    int randint7() {    // randint(0, 7): rng=6, mask=7, masked rejection
        for (;;) {
            uint32_t v = next() & 7u;
            if (v <= 6u) return (int)v;
        }
    }
};
}  // namespace

extern "C" void kernel_launch(void* const* d_in, const int* in_sizes, int n_in,
                              void* d_out, int out_size) {
    const float* x = (const float*)d_in[0];
    float* out     = (float*)d_out;

    IdxPack ip;
    for (int it = 0; it < ITERS; ++it) {
        MT19937 m(42u + (uint32_t)it);
        ip.ii[it] = m.randint7();
        ip.jj[it] = m.randint7();
    }

    dim3 grid1(64, B_);
    pool_kernel<<<grid1, 256>>>(x);

    const int total = B_ * OUTH * OUTW * 32;   // 50176 float4s
    combine_kernel<<<(total + 255) / 256, 256>>>(out, ip);
}

// round 5
// speedup vs baseline: 1.0816x; 1.0816x over previous
#include <cuda_runtime.h>
#include <stdint.h>

#define B_    32
#define HW_   225
#define C_    128
#define OUTH  7
#define OUTW  7
#define ITERS 10
#define NS    4          // row-chunk splits per pooled cell (8 rows each)

// Partial maxes: [NS][B][8*8 cells][128 ch]  = 4 MB device scratch
__device__ float g_part[NS * B_ * 64 * C_];

__device__ __forceinline__ float4 fmax4(float4 a, float4 b) {
    return make_float4(fmaxf(a.x, b.x), fmaxf(a.y, b.y),
                       fmaxf(a.z, b.z), fmaxf(a.w, b.w));
}
__device__ __forceinline__ float neg_inf() { return __int_as_float(0xff800000); }
__device__ __forceinline__ float4 neg4() {
    return make_float4(neg_inf(), neg_inf(), neg_inf(), neg_inf());
}

// -----------------------------------------------------------------------------
// Kernel 1: partial max pool.
// Window = stride = 32, SAME padding (pad_lo=15, pad_hi=16) -> disjoint windows.
// Block = (cell, row-chunk s, batch). 256 threads:
//   lane (tid&31) -> channel quad (float4): warp reads 512B contiguous / pixel
//   rg   (tid>>5) -> one input row: h = h0 + s*8 + rg
// Each thread reduces one row across the window's columns; smem-reduce the 8
// rows; warp 0 writes the chunk's partial max.
// -----------------------------------------------------------------------------
__global__ void __launch_bounds__(256) pool_kernel(const float* __restrict__ x) {
    const int cell = blockIdx.x >> 2;        // 0..63
    const int s    = blockIdx.x & (NS - 1);  // 0..3
    const int b    = blockIdx.y;             // 0..31
    const int i = cell >> 3, j = cell & 7;

    int h0 = i * 32 - 15; if (h0 < 0)   h0 = 0;
    int h1 = i * 32 + 17; if (h1 > HW_) h1 = HW_;
    int w0 = j * 32 - 15; if (w0 < 0)   w0 = 0;
    int w1 = j * 32 + 17; if (w1 > HW_) w1 = HW_;
    const int nw = w1 - w0;

    const int lane = threadIdx.x & 31;
    const int rg   = threadIdx.x >> 5;
    const int h    = h0 + s * 8 + rg;

    float4 a0 = neg4(), a1 = neg4(), a2 = neg4(), a3 = neg4();

    if (h < h1) {
        const float4* __restrict__ p =
            (const float4*)x + ((size_t)((b * HW_ + h) * HW_ + w0)) * 32 + lane;
        if (nw == 32) {
            // interior fast path: 32 independent loads, 4 accumulator chains
            #pragma unroll
            for (int k = 0; k < 8; ++k) {
                a0 = fmax4(a0, __ldcs(p + (k * 4 + 0) * 32));
                a1 = fmax4(a1, __ldcs(p + (k * 4 + 1) * 32));
                a2 = fmax4(a2, __ldcs(p + (k * 4 + 2) * 32));
                a3 = fmax4(a3, __ldcs(p + (k * 4 + 3) * 32));
            }
        } else {
            int w = 0;
            for (; w + 4 <= nw; w += 4) {
                a0 = fmax4(a0, __ldcs(p + (w + 0) * 32));
                a1 = fmax4(a1, __ldcs(p + (w + 1) * 32));
                a2 = fmax4(a2, __ldcs(p + (w + 2) * 32));
                a3 = fmax4(a3, __ldcs(p + (w + 3) * 32));
            }
            for (; w < nw; ++w) a0 = fmax4(a0, __ldcs(p + w * 32));
        }
    }
    float4 acc = fmax4(fmax4(a0, a1), fmax4(a2, a3));

    __shared__ float4 part[8][32];
    part[rg][lane] = acc;
    __syncthreads();

    if (rg == 0) {
        float4 m = part[0][lane];
        #pragma unroll
        for (int k = 1; k < 8; ++k) m = fmax4(m, part[k][lane]);
        ((float4*)g_part)[((s * B_ + b) * 64 + cell) * 32 + lane] = m;
    }
}

// -----------------------------------------------------------------------------
// Kernel 2: reduce NS partials per cell, then the 10-iteration merge/average.
// For iteration it with merge indices (mi, mj):
//   include pooled row r iff r<=mi, row r+1 iff r>=mi  (cols symmetric)
// -----------------------------------------------------------------------------
struct IdxPack { int ii[ITERS]; int jj[ITERS]; };

__global__ void __launch_bounds__(256) combine_kernel(float* __restrict__ out, IdxPack ip) {
    const int t = blockIdx.x * blockDim.x + threadIdx.x;   // [0, 32*7*7*32)
    if (t >= B_ * OUTH * OUTW * 32) return;

    const int q     = t & 31;                // channel quad
    const int cellc = t >> 5;
    const int c = cellc % OUTW;
    const int r = (cellc / OUTW) % OUTH;
    const int b = cellc / (OUTW * OUTH);

    const float4* __restrict__ P = (const float4*)g_part;
    float4 p00 = neg4(), p01 = neg4(), p10 = neg4(), p11 = neg4();
    #pragma unroll
    for (int s = 0; s < NS; ++s) {
        const int base = (s * B_ + b) * 64;
        p00 = fmax4(p00, P[(base + (r    ) * 8 + c    ) * 32 + q]);
        p01 = fmax4(p01, P[(base + (r    ) * 8 + c + 1) * 32 + q]);
        p10 = fmax4(p10, P[(base + (r + 1) * 8 + c    ) * 32 + q]);
        p11 = fmax4(p11, P[(base + (r + 1) * 8 + c + 1) * 32 + q]);
    }

    float4 sum = make_float4(0.f, 0.f, 0.f, 0.f);
    #pragma unroll
    for (int it = 0; it < ITERS; ++it) {
        const int mi = ip.ii[it], mj = ip.jj[it];
        const bool r0 = (r <= mi), r1 = (r >= mi);
        const bool c0 = (c <= mj), c1 = (c >= mj);
        float4 v = neg4();
        if (r0 && c0) v = fmax4(v, p00);
        if (r0 && c1) v = fmax4(v, p01);
        if (r1 && c0) v = fmax4(v, p10);
        if (r1 && c1) v = fmax4(v, p11);
        sum.x += v.x; sum.y += v.y; sum.z += v.z; sum.w += v.w;
    }

    ((float4*)out)[t] = make_float4(sum.x / (float)ITERS, sum.y / (float)ITERS,
                                    sum.z / (float)ITERS, sum.w / (float)ITERS);
}

// -----------------------------------------------------------------------------
// Host: exact replication of np.random.RandomState(seed).randint(0, 7)
// Legacy path: init_genrand seeding; bounded draw uses the 32-bit generator
// with masked rejection (mask=7, reject value 7).
// -----------------------------------------------------------------------------
namespace {
struct MT19937 {
    uint32_t mt[624];
    int idx;
    explicit MT19937(uint32_t s) {
        mt[0] = s;
        for (uint32_t k = 1; k < 624; ++k)
            mt[k] = 1812433253u * (mt[k - 1] ^ (mt[k - 1] >> 30)) + k;
        idx = 624;
    }
    uint32_t next() {
        if (idx >= 624) {
            for (int k = 0; k < 624; ++k) {
                uint32_t y = (mt[k] & 0x80000000u) | (mt[(k + 1) % 624] & 0x7fffffffu);
                uint32_t v = mt[(k + 397) % 624] ^ (y >> 1);
                if (y & 1u) v ^= 0x9908b0dfu;
                mt[k] = v;
            }
            idx = 0;
        }
        uint32_t y = mt[idx++];
        y ^= y >> 11;
        y ^= (y << 7)  & 0x9d2c5680u;
        y ^= (y << 15) & 0xefc60000u;
        y ^= y >> 18;
        return y;
    }
    int randint7() {    // randint(0, 7): masked rejection, mask=7, reject 7
        for (;;) {
            uint32_t v = next() & 7u;
            if (v <= 6u) return (int)v;
        }
    }
};
}  // namespace

extern "C" void kernel_launch(void* const* d_in, const int* in_sizes, int n_in,
                              void* d_out, int out_size) {
    const float* x = (const float*)d_in[0];
    float* out     = (float*)d_out;

    IdxPack ip;
    for (int it = 0; it < ITERS; ++it) {
        MT19937 m(42u + (uint32_t)it);
        ip.ii[it] = m.randint7();
        ip.jj[it] = m.randint7();
    }

    dim3 grid1(64 * NS, B_);
    pool_kernel<<<grid1, 256>>>(x);

    const int total = B_ * OUTH * OUTW * 32;   // 50176 float4s
    combine_kernel<<<(total + 255) / 256, 256>>>(out, ip);
}